// round 2
// baseline (speedup 1.0000x reference)
#include <cuda_runtime.h>
#include <math.h>

#define B 8192
#define D 256
#define P 4096
#define MASKW (B/32)   /* 256 mask words per row */

// ---------------- device globals (no runtime allocation allowed) -------------
__device__ float    g_E[B*D];                 // normalized embeddings (8 MB)
__device__ unsigned g_mask[B*MASKW];          // B x B bitmap (8 MB)
__device__ int      g_flags[B];
__device__ int      g_rows[B];                // compacted list of needed rows
__device__ int      g_NR;
__device__ float    g_EXPM[(size_t)B*B];      // scratch: exp rows per slot (256 MB)
__device__ float    g_S[B];                   // S per actual row index
__device__ float    g_pos[P];
__device__ float    g_SA[P];
__device__ float    g_SB[P];
__device__ float    g_thr;                    // pair threshold (0.2-quantile)
__device__ double   g_partial[P];

// ---------------- clear ------------------------------------------------------
__global__ void k_clear() {
    int idx = blockIdx.x * 256 + threadIdx.x;     // grid covers B*MASKW words
    if (idx < B*MASKW) g_mask[idx] = 0u;
    if (idx < B)       g_flags[idx] = 0;
    if (idx == 0)      g_NR = 0;
}

// ---------------- normalize + diagonal mask ---------------------------------
__global__ void k_normalize(const float* __restrict__ emb) {
    int r = blockIdx.x, t = threadIdx.x;
    __shared__ float red[256];
    float x = emb[r*D + t];
    red[t] = x * x;
    __syncthreads();
    for (int o = 128; o > 0; o >>= 1) { if (t < o) red[t] += red[t+o]; __syncthreads(); }
    float nrm = fmaxf(sqrtf(red[0]), 1e-8f);
    g_E[r*D + t] = x / nrm;
    if (t == 0) g_mask[(size_t)r*MASKW + (r>>5)] = (1u << (r & 31));  // diag bit
}

// ---------------- pairs: pos values, mask bits, row flags --------------------
__global__ void k_pairs(const int* __restrict__ pp) {
    int w = threadIdx.x >> 5, lane = threadIdx.x & 31;
    int p = blockIdx.x * 8 + w;
    if (p >= P) return;
    int i = pp[p*2], j = pp[p*2+1];
    const float* ei = &g_E[(size_t)i*D];
    const float* ej = &g_E[(size_t)j*D];
    float s = 0.f;
    #pragma unroll
    for (int q = 0; q < 8; q++) { int d = lane + 32*q; s += ei[d] * ej[d]; }
    #pragma unroll
    for (int o = 16; o > 0; o >>= 1) s += __shfl_xor_sync(0xffffffffu, s, o);
    if (lane == 0) {
        g_pos[p] = __expf(s * 5.0f);   // 1/BETA = 5
        atomicOr(&g_mask[(size_t)i*MASKW + (j>>5)], 1u << (j & 31));
        atomicOr(&g_mask[(size_t)j*MASKW + (i>>5)], 1u << (i & 31));
        g_flags[i] = 1; g_flags[j] = 1;
    }
}

// ---------------- compact needed rows ----------------------------------------
__global__ void k_compact() {
    for (int r = threadIdx.x; r < B; r += blockDim.x)
        if (g_flags[r]) { int s = atomicAdd(&g_NR, 1); g_rows[s] = r; }
}

// ---------------- SGEMM: EXPM[slot][c] = masked exp(e[row]·e[c] / beta) ------
// 128x128 block tile, 8x8 per thread, K-tile 16, 256 threads.
__global__ void __launch_bounds__(256) k_gemm() {
    int nr = g_NR;
    int rb = blockIdx.y, cb = blockIdx.x;
    if (rb * 128 >= nr) return;
    __shared__ float As[16][128];
    __shared__ float Bs[16][128];
    __shared__ int rows[128];
    int tid = threadIdx.x;
    for (int i = tid; i < 128; i += 256) {
        int s = rb*128 + i;
        rows[i] = (s < nr) ? g_rows[s] : g_rows[0];
    }
    __syncthreads();
    float acc[8][8];
    #pragma unroll
    for (int i = 0; i < 8; i++)
        #pragma unroll
        for (int j = 0; j < 8; j++) acc[i][j] = 0.f;
    int tx = tid & 15, ty = tid >> 4;

    for (int kt = 0; kt < 16; kt++) {
        int kb = kt * 16;
        #pragma unroll
        for (int l = 0; l < 2; l++) {
            int lin = tid*2 + l;           // 0..511
            int m   = lin >> 2;            // 0..127
            int kq  = (lin & 3) * 4;       // 0,4,8,12
            float4 av = *(const float4*)&g_E[(size_t)rows[m]*D + kb + kq];
            As[kq+0][m] = av.x; As[kq+1][m] = av.y; As[kq+2][m] = av.z; As[kq+3][m] = av.w;
            float4 bv = *(const float4*)&g_E[(size_t)(cb*128 + m)*D + kb + kq];
            Bs[kq+0][m] = bv.x; Bs[kq+1][m] = bv.y; Bs[kq+2][m] = bv.z; Bs[kq+3][m] = bv.w;
        }
        __syncthreads();
        #pragma unroll
        for (int k = 0; k < 16; k++) {
            float a[8], b[8];
            *(float4*)&a[0] = *(const float4*)&As[k][ty*8];
            *(float4*)&a[4] = *(const float4*)&As[k][ty*8+4];
            *(float4*)&b[0] = *(const float4*)&Bs[k][tx*8];
            *(float4*)&b[4] = *(const float4*)&Bs[k][tx*8+4];
            #pragma unroll
            for (int i = 0; i < 8; i++)
                #pragma unroll
                for (int j = 0; j < 8; j++)
                    acc[i][j] = fmaf(a[i], b[j], acc[i][j]);
        }
        __syncthreads();
    }
    // epilogue: exp + mask + store
    #pragma unroll
    for (int i = 0; i < 8; i++) {
        int s = rb*128 + ty*8 + i;
        if (s >= nr) continue;
        int r = rows[ty*8 + i];
        const unsigned* mrow = &g_mask[(size_t)r*MASKW];
        int c0 = cb*128 + tx*8;
        size_t ob = (size_t)s*B + c0;
        #pragma unroll
        for (int j = 0; j < 8; j++) {
            int c = c0 + j;
            float v = __expf(acc[i][j] * 5.0f);
            if ((mrow[c>>5] >> (c & 31)) & 1u) v = 0.0f;
            g_EXPM[ob + j] = v;
        }
    }
}

// ---------------- exact radix select (k-th smallest, 0-based) ----------------
__device__ unsigned radix_select(const unsigned* sv, int n, int k,
                                 unsigned* hist, unsigned* spre, int* skrem) {
    int t = threadIdx.x;
    if (t == 0) { *spre = 0u; *skrem = k; }
    __syncthreads();
    for (int shift = 24; shift >= 0; shift -= 8) {
        hist[t] = 0u;                       // blockDim == 256
        __syncthreads();
        unsigned pre = *spre;
        unsigned hm  = (shift == 24) ? 0u : (0xFFFFFFFFu << (shift + 8));
        for (int c = t; c < n; c += 256) {
            unsigned u = sv[c];
            if ((u & hm) == pre) atomicAdd(&hist[(u >> shift) & 255], 1u);
        }
        __syncthreads();
        if (t == 0) {
            unsigned cum = 0; int kr = *skrem; unsigned chosen = 255;
            for (int b = 0; b < 256; b++) {
                unsigned h = hist[b];
                if (cum + h > (unsigned)kr) { chosen = (unsigned)b; break; }
                cum += h;
            }
            *skrem = kr - (int)cum;
            *spre  = pre | (chosen << shift);
        }
        __syncthreads();
    }
    return *spre;
}

// ---------------- per-row: order stats 6552/6553 -> threshold -> S -----------
__global__ void __launch_bounds__(256) k_select() {
    __shared__ unsigned sv[B];        // 32 KB
    __shared__ unsigned hist[256];
    __shared__ unsigned spre; __shared__ int skrem;
    __shared__ float red[256];
    __shared__ unsigned scnt, smn;
    int slot = blockIdx.x;
    if (slot >= g_NR) return;
    int t = threadIdx.x;
    size_t base = (size_t)slot * B;
    for (int c = t; c < B; c += 256) sv[c] = __float_as_uint(g_EXPM[base + c]);
    __syncthreads();
    unsigned u0 = radix_select(sv, B, 6552, hist, &spre, &skrem);
    if (t == 0) { scnt = 0u; smn = 0xFFFFFFFFu; }
    __syncthreads();
    unsigned cnt = 0, mn = 0xFFFFFFFFu;
    for (int c = t; c < B; c += 256) {
        unsigned u = sv[c];
        if (u <= u0) cnt++;
        else if (u < mn) mn = u;
    }
    atomicAdd(&scnt, cnt);
    atomicMin(&smn, mn);
    __syncthreads();
    unsigned u1 = (scnt >= 6554u) ? u0 : smn;   // v[6553]
    float v0 = __uint_as_float(u0), v1 = __uint_as_float(u1);
    float thr = v0 + 0.8f * (v1 - v0);          // any frac in (0,1) yields same S
    float s = 0.f;
    for (int c = t; c < B; c += 256) {
        float v = __uint_as_float(sv[c]);
        if (v >= thr) s += v;
    }
    red[t] = s; __syncthreads();
    for (int o = 128; o > 0; o >>= 1) { if (t < o) red[t] += red[t+o]; __syncthreads(); }
    if (t == 0) g_S[g_rows[slot]] = red[0];
}

// ---------------- pair threshold (exact 819-th smallest of pos) --------------
__global__ void k_pairthr() {
    __shared__ unsigned pv[P];        // 16 KB
    __shared__ unsigned hist[256];
    __shared__ unsigned spre; __shared__ int skrem;
    int t = threadIdx.x;
    for (int c = t; c < P; c += 256) pv[c] = __float_as_uint(g_pos[c]);
    __syncthreads();
    unsigned u = radix_select(pv, P, 819, hist, &spre, &skrem);
    if (t == 0) g_thr = __uint_as_float(u);
}

// ---------------- gather S per pair column -----------------------------------
__global__ void k_gather(const int* __restrict__ pp) {
    int c = blockIdx.x * 256 + threadIdx.x;
    if (c < P) { g_SA[c] = g_S[pp[c*2]]; g_SB[c] = g_S[pp[c*2+1]]; }
}

// ---------------- loss terms per (active) pair -------------------------------
__global__ void k_loss() {
    int p = blockIdx.x, t = threadIdx.x;
    __shared__ float red[256];
    float pos = g_pos[p];
    if (pos > g_thr) { if (t == 0) g_partial[p] = 0.0; return; }
    float inv = 1.0f / pos;
    float s = 0.f;
    for (int c = t; c < P; c += 256)
        s += log1pf(g_SA[c] * inv) + log1pf(g_SB[c] * inv);
    red[t] = s; __syncthreads();
    for (int o = 128; o > 0; o >>= 1) { if (t < o) red[t] += red[t+o]; __syncthreads(); }
    if (t == 0) g_partial[p] = (double)red[0];
}

// ---------------- deterministic final reduction ------------------------------
__global__ void k_final(float* out) {
    __shared__ double red[256];
    int t = threadIdx.x;
    double s = 0.0;
    for (int p = t; p < P; p += 256) s += g_partial[p];
    red[t] = s; __syncthreads();
    for (int o = 128; o > 0; o >>= 1) { if (t < o) red[t] += red[t+o]; __syncthreads(); }
    if (t == 0) out[0] = (float)(red[0] / (2.0 * (double)P));
}

// ---------------- launch -----------------------------------------------------
extern "C" void kernel_launch(void* const* d_in, const int* in_sizes, int n_in,
                              void* d_out, int out_size) {
    const float* emb;
    const int*   pairs;
    if (in_sizes[0] == B*D) { emb = (const float*)d_in[0]; pairs = (const int*)d_in[1]; }
    else                    { emb = (const float*)d_in[1]; pairs = (const int*)d_in[0]; }
    float* out = (float*)d_out;

    k_clear    <<<(B*MASKW + 255)/256, 256>>>();
    k_normalize<<<B, 256>>>(emb);
    k_pairs    <<<P/8, 256>>>(pairs);
    k_compact  <<<1, 256>>>();
    k_gemm     <<<dim3(64, 64), 256>>>();
    k_select   <<<B, 256>>>();
    k_pairthr  <<<1, 256>>>();
    k_gather   <<<(P + 255)/256, 256>>>(pairs);
    k_loss     <<<P, 256>>>();
    k_final    <<<1, 256>>>(out);
}

// round 4
// speedup vs baseline: 1.5183x; 1.5183x over previous
#include <cuda_runtime.h>
#include <cuda_fp16.h>
#include <math.h>
#include <stdint.h>

#define B 8192
#define D 256
#define P 4096
#define MASKW 256          /* B/32 mask words per row */
#define LDA 264            /* smem half-stride: 256 + 8 pad */

// ---------------- device globals (no runtime allocation allowed) -------------
__device__ float    g_E[B*D];                 // normalized embeddings fp32 (8 MB)
__device__ __half   g_Eh[B*D];                // normalized embeddings fp16 (4 MB)
__device__ unsigned g_mask[(size_t)B*MASKW];  // B x B bitmap (8 MB)
__device__ int      g_flags[B];
__device__ int      g_rows[B];
__device__ int      g_NR;
__device__ float    g_EXPM[(size_t)B*B];      // scratch (256 MB)
__device__ float    g_S[B];
__device__ float    g_pos[P];
__device__ float    g_thr;
__device__ double   g_stats[5];               // kact, P1, P2, P3, sum(log pos)

// ---------------- clear ------------------------------------------------------
__global__ void k_clear() {
    int idx = blockIdx.x * 256 + threadIdx.x;
    if (idx < B*MASKW) g_mask[idx] = 0u;
    if (idx < B)       g_flags[idx] = 0;
    if (idx == 0)      g_NR = 0;
}

// ---------------- normalize + fp16 copy + diagonal mask ----------------------
__global__ void k_normalize(const float* __restrict__ emb) {
    int r = blockIdx.x, t = threadIdx.x;
    __shared__ float red[256];
    float x = emb[r*D + t];
    red[t] = x * x;
    __syncthreads();
    for (int o = 128; o > 0; o >>= 1) { if (t < o) red[t] += red[t+o]; __syncthreads(); }
    float nrm = fmaxf(sqrtf(red[0]), 1e-8f);
    float e = x / nrm;
    g_E [r*D + t] = e;
    g_Eh[r*D + t] = __float2half_rn(e);
    if (t == 0) g_mask[(size_t)r*MASKW + (r>>5)] = (1u << (r & 31));
}

// ---------------- pairs: exact fp32 pos, mask bits, row flags ----------------
__global__ void k_pairs(const int* __restrict__ pp) {
    int w = threadIdx.x >> 5, lane = threadIdx.x & 31;
    int p = blockIdx.x * 8 + w;
    if (p >= P) return;
    int i = pp[p*2], j = pp[p*2+1];
    const float* ei = &g_E[(size_t)i*D];
    const float* ej = &g_E[(size_t)j*D];
    float s = 0.f;
    #pragma unroll
    for (int q = 0; q < 8; q++) { int d = lane + 32*q; s += ei[d] * ej[d]; }
    #pragma unroll
    for (int o = 16; o > 0; o >>= 1) s += __shfl_xor_sync(0xffffffffu, s, o);
    if (lane == 0) {
        g_pos[p] = __expf(s * 5.0f);
        atomicOr(&g_mask[(size_t)i*MASKW + (j>>5)], 1u << (j & 31));
        atomicOr(&g_mask[(size_t)j*MASKW + (i>>5)], 1u << (i & 31));
        g_flags[i] = 1; g_flags[j] = 1;
    }
}

// ---------------- compact needed rows ----------------------------------------
__global__ void k_compact() {
    int r = blockIdx.x * 256 + threadIdx.x;
    if (r < B && g_flags[r]) { int s = atomicAdd(&g_NR, 1); g_rows[s] = r; }
}

// =================== HMMA GEMM: EXPM[s][c] = masked exp(5 e[row_s] . e[c]) ===
// 128x128 CTA tile, 8 warps (2m x 4n), warp tile 64x32, m16n8k16 fp16->fp32.
__device__ __forceinline__ void mma16816(float* c, const uint32_t* a, const uint32_t* b) {
    asm volatile(
        "mma.sync.aligned.m16n8k16.row.col.f32.f16.f16.f32 "
        "{%0,%1,%2,%3}, {%4,%5,%6,%7}, {%8,%9}, {%0,%1,%2,%3};"
        : "+f"(c[0]), "+f"(c[1]), "+f"(c[2]), "+f"(c[3])
        : "r"(a[0]), "r"(a[1]), "r"(a[2]), "r"(a[3]), "r"(b[0]), "r"(b[1]));
}

__global__ void __launch_bounds__(256) k_gemm_mma() {
    int nr = g_NR;
    int rb = blockIdx.y, cb = blockIdx.x;
    if (rb * 128 >= nr) return;
    extern __shared__ __align__(16) __half dsm[];
    __half* As = dsm;                 // 128 x LDA
    __half* Bs = dsm + 128*LDA;       // 128 x LDA
    __shared__ int rows_s[128];
    int t = threadIdx.x;

    for (int i = t; i < 128; i += 256) {
        int s = rb*128 + i;
        rows_s[i] = (s < nr) ? g_rows[s] : g_rows[0];
    }
    __syncthreads();
    #pragma unroll
    for (int i = 0; i < 16; ++i) {
        int q = t + i*256;                 // 0..4095
        int row = q >> 5, seg = q & 31;    // 128 rows x 32 x uint4
        *(uint4*)&As[row*LDA + seg*8] =
            *(const uint4*)&g_Eh[(size_t)rows_s[row]*D + seg*8];
        *(uint4*)&Bs[row*LDA + seg*8] =
            *(const uint4*)&g_Eh[(size_t)(cb*128 + row)*D + seg*8];
    }
    __syncthreads();

    int wid = t >> 5, lane = t & 31;
    int wm = wid >> 2, wn = wid & 3;       // 2 x 4 warp grid
    int lr = lane >> 2, lc = lane & 3;

    float acc[4][4][4];
    #pragma unroll
    for (int mt = 0; mt < 4; ++mt)
        #pragma unroll
        for (int nt = 0; nt < 4; ++nt)
            #pragma unroll
            for (int q = 0; q < 4; ++q) acc[mt][nt][q] = 0.f;

    #pragma unroll
    for (int kt = 0; kt < 16; ++kt) {
        int k0 = kt*16 + lc*2;
        uint32_t a[4][4], b[4][2];
        #pragma unroll
        for (int mt = 0; mt < 4; ++mt) {
            const __half* ap = &As[(wm*64 + mt*16 + lr)*LDA + k0];
            a[mt][0] = *(const uint32_t*)ap;
            a[mt][1] = *(const uint32_t*)(ap + 8*LDA);
            a[mt][2] = *(const uint32_t*)(ap + 8);
            a[mt][3] = *(const uint32_t*)(ap + 8*LDA + 8);
        }
        #pragma unroll
        for (int nt = 0; nt < 4; ++nt) {
            const __half* bp = &Bs[(wn*32 + nt*8 + lr)*LDA + k0];
            b[nt][0] = *(const uint32_t*)bp;
            b[nt][1] = *(const uint32_t*)(bp + 8);
        }
        #pragma unroll
        for (int mt = 0; mt < 4; ++mt)
            #pragma unroll
            for (int nt = 0; nt < 4; ++nt)
                mma16816(acc[mt][nt], a[mt], b[nt]);
    }

    // epilogue: exp + mask + float2 stores
    int cbase = cb*128 + wn*32;
    int mword = cb*4 + wn;                    // mask word covering [cbase, cbase+32)
    #pragma unroll
    for (int mt = 0; mt < 4; ++mt) {
        #pragma unroll
        for (int h = 0; h < 2; ++h) {
            int sl = rb*128 + wm*64 + mt*16 + lr + h*8;
            if (sl >= nr) continue;
            int r = rows_s[wm*64 + mt*16 + lr + h*8];
            unsigned mw = g_mask[(size_t)r*MASKW + mword];
            size_t ob = (size_t)sl * B + cbase;
            #pragma unroll
            for (int nt = 0; nt < 4; ++nt) {
                int bi = nt*8 + lc*2;
                float v0 = ((mw >> bi)     & 1u) ? 0.f : __expf(acc[mt][nt][h*2+0] * 5.0f);
                float v1 = ((mw >> (bi+1)) & 1u) ? 0.f : __expf(acc[mt][nt][h*2+1] * 5.0f);
                float2 v = make_float2(v0, v1);
                *(float2*)&g_EXPM[ob + bi] = v;
            }
        }
    }
}

// ---------------- exact radix select (k-th smallest), parallel scan ----------
__device__ unsigned radix_select(const unsigned* sv, int n, int k,
                                 unsigned* hist, unsigned* spre, int* skrem) {
    int t = threadIdx.x;
    if (t == 0) { *spre = 0u; *skrem = k; }
    __syncthreads();
    for (int shift = 24; shift >= 0; shift -= 8) {
        hist[t] = 0u;
        __syncthreads();
        unsigned pre = *spre;
        unsigned hm  = (shift == 24) ? 0u : (0xFFFFFFFFu << (shift + 8));
        for (int c = t; c < n; c += 256) {
            unsigned u = sv[c];
            if ((u & hm) == pre) atomicAdd(&hist[(u >> shift) & 255], 1u);
        }
        __syncthreads();
        // inclusive Hillis-Steele scan over 256 buckets
        #pragma unroll
        for (int o = 1; o < 256; o <<= 1) {
            unsigned v = (t >= o) ? hist[t-o] : 0u;
            __syncthreads();
            hist[t] += v;
            __syncthreads();
        }
        unsigned kr  = (unsigned)*skrem;
        unsigned cin = hist[t];
        unsigned cex = t ? hist[t-1] : 0u;
        __syncthreads();
        if (cin > kr && cex <= kr) {
            *spre  = pre | ((unsigned)t << shift);
            *skrem = (int)(kr - cex);
        }
        __syncthreads();
    }
    return *spre;
}

// ---------------- per-row order stats 6552/6553 -> S (per slot) --------------
__global__ void __launch_bounds__(256) k_select() {
    __shared__ unsigned sv[B];        // 32 KB
    __shared__ unsigned hist[256];
    __shared__ unsigned spre; __shared__ int skrem;
    __shared__ float red[256];
    __shared__ unsigned scnt, smn;
    int slot = blockIdx.x;
    if (slot >= g_NR) return;
    int t = threadIdx.x;
    size_t base = (size_t)slot * B;
    const uint4* src = (const uint4*)&g_EXPM[base];
    for (int c = t; c < B/4; c += 256) ((uint4*)sv)[c] = src[c];
    __syncthreads();
    unsigned u0 = radix_select(sv, B, 6552, hist, &spre, &skrem);
    if (t == 0) { scnt = 0u; smn = 0xFFFFFFFFu; }
    __syncthreads();
    unsigned cnt = 0, mn = 0xFFFFFFFFu;
    for (int c = t; c < B; c += 256) {
        unsigned u = sv[c];
        if (u <= u0) cnt++;
        else if (u < mn) mn = u;
    }
    atomicAdd(&scnt, cnt);
    atomicMin(&smn, mn);
    __syncthreads();
    unsigned u1 = (scnt >= 6554u) ? u0 : smn;   // v[6553]
    float v0 = __uint_as_float(u0), v1 = __uint_as_float(u1);
    float thr = v0 + 0.8f * (v1 - v0);          // S invariant to the exact frac
    float s = 0.f;
    for (int c = t; c < B; c += 256) {
        float v = __uint_as_float(sv[c]);
        if (v >= thr) s += v;
    }
    red[t] = s; __syncthreads();
    for (int o = 128; o > 0; o >>= 1) { if (t < o) red[t] += red[t+o]; __syncthreads(); }
    if (t == 0) g_S[g_rows[slot]] = red[0];
}

// ---------------- pair threshold (exact 819th smallest) ----------------------
__global__ void k_pairthr() {
    __shared__ unsigned pv[P];
    __shared__ unsigned hist[256];
    __shared__ unsigned spre; __shared__ int skrem;
    int t = threadIdx.x;
    for (int c = t; c < P; c += 256) pv[c] = __float_as_uint(g_pos[c]);
    __syncthreads();
    unsigned u = radix_select(pv, P, 819, hist, &spre, &skrem);
    if (t == 0) g_thr = __uint_as_float(u);
}

// ---------------- active-pair moments ----------------------------------------
__global__ void k_stats() {
    __shared__ double r1[256], r2[256], r3[256], r4[256];
    __shared__ int rk[256];
    int t = threadIdx.x;
    float thr = g_thr;
    double p1 = 0, p2 = 0, p3 = 0, L = 0; int k = 0;
    for (int p = t; p < P; p += 256) {
        float v = g_pos[p];
        if (v <= thr) {
            double dv = (double)v;
            p1 += dv; p2 += dv*dv; p3 += dv*dv*dv; L += log(dv); k++;
        }
    }
    r1[t] = p1; r2[t] = p2; r3[t] = p3; r4[t] = L; rk[t] = k;
    __syncthreads();
    for (int o = 128; o > 0; o >>= 1) {
        if (t < o) { r1[t]+=r1[t+o]; r2[t]+=r2[t+o]; r3[t]+=r3[t+o]; r4[t]+=r4[t+o]; rk[t]+=rk[t+o]; }
        __syncthreads();
    }
    if (t == 0) {
        g_stats[0] = (double)rk[0]; g_stats[1] = r1[0]; g_stats[2] = r2[0];
        g_stats[3] = r3[0]; g_stats[4] = r4[0];
    }
}

// ---------------- closed-form loss -------------------------------------------
// sum_p log1p(S/pos_p) = kact*log(S) - sum log pos + sum log1p(pos_p/S);
// pos_p/S < 0.02 -> 3-term Taylor, error <= x^4/4 ~ 4e-8; exact fallback else.
__global__ void k_final(const int* __restrict__ pp, float* __restrict__ out) {
    __shared__ double red[256];
    int t = threadIdx.x;
    double kact = g_stats[0], P1 = g_stats[1], P2 = g_stats[2], P3 = g_stats[3], L = g_stats[4];
    float thr = g_thr;
    double acc = 0.0;
    for (int s = t; s < 2*P; s += 256) {
        int pidx = s >> 1, side = s & 1;
        double S = (double)g_S[pp[pidx*2 + side]];
        if ((double)thr / S < 0.02) {
            double inv = 1.0 / S;
            acc += kact*log(S) - L + P1*inv - 0.5*P2*inv*inv + (1.0/3.0)*P3*inv*inv*inv;
        } else {
            for (int p = 0; p < P; ++p) {
                float pv = g_pos[p];
                if (pv <= thr) acc += log1p(S / (double)pv);
            }
        }
    }
    red[t] = acc; __syncthreads();
    for (int o = 128; o > 0; o >>= 1) { if (t < o) red[t] += red[t+o]; __syncthreads(); }
    if (t == 0) out[0] = (float)(red[0] / (2.0 * (double)P));
}

// ---------------- launch -----------------------------------------------------
extern "C" void kernel_launch(void* const* d_in, const int* in_sizes, int n_in,
                              void* d_out, int out_size) {
    const float* emb;
    const int*   pairs;
    if (in_sizes[0] == B*D) { emb = (const float*)d_in[0]; pairs = (const int*)d_in[1]; }
    else                    { emb = (const float*)d_in[1]; pairs = (const int*)d_in[0]; }
    float* out = (float*)d_out;

    static int gemm_smem = 2 * 128 * LDA * (int)sizeof(__half);   // 135168
    cudaFuncSetAttribute(k_gemm_mma, cudaFuncAttributeMaxDynamicSharedMemorySize, gemm_smem);

    k_clear    <<<(B*MASKW + 255)/256, 256>>>();
    k_normalize<<<B, 256>>>(emb);
    k_pairs    <<<P/8, 256>>>(pairs);
    k_compact  <<<B/256, 256>>>();
    k_gemm_mma <<<dim3(64, 64), 256, gemm_smem>>>();
    k_select   <<<B, 256>>>();
    k_pairthr  <<<1, 256>>>();
    k_stats    <<<1, 256>>>();
    k_final    <<<1, 256>>>(pairs, out);
}

// round 5
// speedup vs baseline: 1.8638x; 1.2276x over previous
#include <cuda_runtime.h>
#include <cuda_fp16.h>
#include <math.h>
#include <stdint.h>

#define B 8192
#define D 256
#define P 4096
#define MASKW 256                      /* B/32 mask words per row */
#define LDC 136                        /* chunk smem stride in halves (128+8) */
#define CHUNK_BYTES (128*LDC*2)        /* 34816 per matrix per stage */
#define STAGE_BYTES (2*CHUNK_BYTES)    /* A+B: 69632 */
#define GEMM_SMEM   (2*STAGE_BYTES)    /* 139264 */

// ---------------- device globals (no runtime allocation allowed) -------------
__device__ float    g_E[B*D];                    // normalized fp32 (8 MB)
__device__ __half   g_Eh[B*D];                   // normalized fp16 (4 MB)
__device__ unsigned g_mask[(size_t)B*MASKW];     // B x B bitmap (8 MB)
__device__ int      g_flags[B];
__device__ int      g_rows[B];
__device__ int      g_NR;
__device__ unsigned short g_KEY[(size_t)B*B];    // u16 ordered cos keys (128 MB)
__device__ float    g_S[B];
__device__ float    g_pos[P];
__device__ float    g_thr;
__device__ double   g_stats[5];                  // kact, P1, P2, P3, sum(log pos)

// ---------------- helpers ----------------------------------------------------
__device__ __forceinline__ uint32_t smem_u32(const void* p) {
    uint32_t a;
    asm("{ .reg .u64 t; cvta.to.shared.u64 t, %1; cvt.u32.u64 %0, t; }" : "=r"(a) : "l"(p));
    return a;
}
__device__ __forceinline__ void cp_async16(uint32_t dst, const void* src) {
    asm volatile("cp.async.cg.shared.global [%0], [%1], 16;" :: "r"(dst), "l"(src));
}
__device__ __forceinline__ void ldsm_x4(uint32_t* r, uint32_t addr) {
    asm volatile("ldmatrix.sync.aligned.m8n8.x4.shared.b16 {%0,%1,%2,%3}, [%4];"
        : "=r"(r[0]), "=r"(r[1]), "=r"(r[2]), "=r"(r[3]) : "r"(addr));
}
__device__ __forceinline__ void mma16816(float* c, const uint32_t* a, const uint32_t* b) {
    asm volatile(
        "mma.sync.aligned.m16n8k16.row.col.f32.f16.f16.f32 "
        "{%0,%1,%2,%3}, {%4,%5,%6,%7}, {%8,%9}, {%0,%1,%2,%3};"
        : "+f"(c[0]), "+f"(c[1]), "+f"(c[2]), "+f"(c[3])
        : "r"(a[0]), "r"(a[1]), "r"(a[2]), "r"(a[3]), "r"(b[0]), "r"(b[1]));
}
// order-preserving u16 key of fp16 value
__device__ __forceinline__ unsigned short enc_key(float c) {
    unsigned short h = __half_as_ushort(__float2half_rn(c));
    return (h & 0x8000) ? (unsigned short)(~h) : (unsigned short)(h | 0x8000);
}
__device__ __forceinline__ float dec_key(unsigned k) {
    unsigned short h = (k & 0x8000u) ? (unsigned short)(k & 0x7FFFu) : (unsigned short)(~k);
    return __half2float(__ushort_as_half(h));
}
#define KEY_MASKED 0x03FFu   /* enc(-inf): decodes to -inf, exp -> 0 */

// ---------------- clear ------------------------------------------------------
__global__ void k_clear() {
    int idx = blockIdx.x * 256 + threadIdx.x;
    if (idx < B*MASKW) g_mask[idx] = 0u;
    if (idx < B)       g_flags[idx] = 0;
    if (idx == 0)      g_NR = 0;
}

// ---------------- normalize + fp16 copy + diagonal mask ----------------------
__global__ void k_normalize(const float* __restrict__ emb) {
    int r = blockIdx.x, t = threadIdx.x;
    __shared__ float red[256];
    float x = emb[r*D + t];
    red[t] = x * x;
    __syncthreads();
    for (int o = 128; o > 0; o >>= 1) { if (t < o) red[t] += red[t+o]; __syncthreads(); }
    float nrm = fmaxf(sqrtf(red[0]), 1e-8f);
    float e = x / nrm;
    g_E [r*D + t] = e;
    g_Eh[r*D + t] = __float2half_rn(e);
    if (t == 0) g_mask[(size_t)r*MASKW + (r>>5)] = (1u << (r & 31));
}

// ---------------- pairs: exact fp32 pos, mask bits, row flags ----------------
__global__ void k_pairs(const int* __restrict__ pp) {
    int w = threadIdx.x >> 5, lane = threadIdx.x & 31;
    int p = blockIdx.x * 8 + w;
    if (p >= P) return;
    int i = pp[p*2], j = pp[p*2+1];
    const float* ei = &g_E[(size_t)i*D];
    const float* ej = &g_E[(size_t)j*D];
    float s = 0.f;
    #pragma unroll
    for (int q = 0; q < 8; q++) { int d = lane + 32*q; s += ei[d] * ej[d]; }
    #pragma unroll
    for (int o = 16; o > 0; o >>= 1) s += __shfl_xor_sync(0xffffffffu, s, o);
    if (lane == 0) {
        g_pos[p] = __expf(s * 5.0f);
        atomicOr(&g_mask[(size_t)i*MASKW + (j>>5)], 1u << (j & 31));
        atomicOr(&g_mask[(size_t)j*MASKW + (i>>5)], 1u << (i & 31));
        g_flags[i] = 1; g_flags[j] = 1;
    }
}

// ---------------- compact needed rows (warp-aggregated atomics) --------------
__global__ void k_compact() {
    int r = blockIdx.x * 256 + threadIdx.x;
    int f = (r < B) ? g_flags[r] : 0;
    unsigned bal = __ballot_sync(0xffffffffu, f);
    int lane = threadIdx.x & 31;
    int base = 0;
    if (lane == 0 && bal) base = atomicAdd(&g_NR, __popc(bal));
    base = __shfl_sync(0xffffffffu, base, 0);
    if (f) g_rows[base + __popc(bal & ((1u << lane) - 1u))] = r;
}

// =================== HMMA GEMM -> u16 keys of cos ============================
// 128x128 CTA tile, 4 warps (2x2) of 64x64, m16n8k16, ldmatrix.x4,
// 2 K-chunks of 128 double-buffered via cp.async.
__global__ void __launch_bounds__(128) k_gemm_mma() {
    int nr = g_NR;
    int rb = blockIdx.y, cb = blockIdx.x;
    if (rb * 128 >= nr) return;
    extern __shared__ __align__(16) char dsm[];
    __shared__ int rows_s[128];
    int t = threadIdx.x;
    {
        int s = rb*128 + t;
        rows_s[t] = (s < nr) ? g_rows[s] : g_rows[0];
    }
    __syncthreads();
    uint32_t sb = smem_u32(dsm);

    #pragma unroll
    for (int c = 0; c < 2; ++c) {
        uint32_t stg = sb + c*STAGE_BYTES;
        #pragma unroll
        for (int i = 0; i < 16; ++i) {
            int q = t + i*128;                 // 0..2047
            int row = q >> 4, seg = q & 15;
            cp_async16(stg + row*(LDC*2) + seg*16,
                       &g_Eh[(size_t)rows_s[row]*D + c*128 + seg*8]);
            cp_async16(stg + CHUNK_BYTES + row*(LDC*2) + seg*16,
                       &g_Eh[(size_t)(cb*128 + row)*D + c*128 + seg*8]);
        }
        asm volatile("cp.async.commit_group;" ::: "memory");
    }

    int wid = t >> 5, lane = t & 31;
    int wm = wid >> 1, wn = wid & 1;          // 2x2 warp grid, 64x64 tiles
    float acc[4][8][4];
    #pragma unroll
    for (int mt = 0; mt < 4; ++mt)
        #pragma unroll
        for (int nt = 0; nt < 8; ++nt)
            #pragma unroll
            for (int q = 0; q < 4; ++q) acc[mt][nt][q] = 0.f;

    #pragma unroll
    for (int c = 0; c < 2; ++c) {
        if (c == 0) asm volatile("cp.async.wait_group 1;" ::: "memory");
        else        asm volatile("cp.async.wait_group 0;" ::: "memory");
        __syncthreads();
        uint32_t Ab = sb + c*STAGE_BYTES;
        uint32_t Bb = Ab + CHUNK_BYTES;
        #pragma unroll
        for (int kt = 0; kt < 8; ++kt) {
            int k0 = kt*16;
            uint32_t a[4][4], bfr[4][4];
            #pragma unroll
            for (int mt = 0; mt < 4; ++mt) {
                uint32_t ad = Ab + (uint32_t)(wm*64 + mt*16 + (lane & 15))*(LDC*2)
                                 + (uint32_t)(k0 + (lane >> 4)*8)*2;
                ldsm_x4(a[mt], ad);
            }
            #pragma unroll
            for (int n2 = 0; n2 < 4; ++n2) {
                int q = lane >> 3, l8 = lane & 7;
                int rowb = wn*64 + n2*16 + ((q >> 1) << 3) + l8;
                uint32_t bd = Bb + (uint32_t)rowb*(LDC*2) + (uint32_t)(k0 + (q & 1)*8)*2;
                ldsm_x4(bfr[n2], bd);
            }
            #pragma unroll
            for (int mt = 0; mt < 4; ++mt)
                #pragma unroll
                for (int nt = 0; nt < 8; ++nt) {
                    uint32_t b2[2] = { bfr[nt>>1][(nt&1)*2], bfr[nt>>1][(nt&1)*2 + 1] };
                    mma16816(acc[mt][nt], a[mt], b2);
                }
        }
    }

    // epilogue: encode keys + mask + packed u16x2 stores
    int lr = lane >> 2, lc2 = (lane & 3) * 2;
    #pragma unroll
    for (int mt = 0; mt < 4; ++mt)
        #pragma unroll
        for (int h = 0; h < 2; ++h) {
            int lrow = wm*64 + mt*16 + lr + h*8;
            int sl = rb*128 + lrow;
            if (sl >= nr) continue;
            int r = rows_s[lrow];
            unsigned mw0 = g_mask[(size_t)r*MASKW + cb*4 + wn*2];
            unsigned mw1 = g_mask[(size_t)r*MASKW + cb*4 + wn*2 + 1];
            size_t ob = (size_t)sl*B + (size_t)(cb*128 + wn*64);
            #pragma unroll
            for (int nt = 0; nt < 8; ++nt) {
                int bpos = nt*8 + lc2;
                unsigned mw = (bpos < 32) ? mw0 : mw1;
                int bit = bpos & 31;
                unsigned short k0 = ((mw >> bit) & 1u)
                    ? (unsigned short)KEY_MASKED : enc_key(acc[mt][nt][h*2]);
                unsigned short k1 = ((mw >> (bit+1)) & 1u)
                    ? (unsigned short)KEY_MASKED : enc_key(acc[mt][nt][h*2 + 1]);
                *(unsigned*)&g_KEY[ob + bpos] = (unsigned)k0 | ((unsigned)k1 << 16);
            }
        }
}

// ---------------- per-row: rank-6553 key -> S --------------------------------
__global__ void __launch_bounds__(256) k_select() {
    __shared__ unsigned short sv[B];      // 16 KB
    __shared__ unsigned hist[256];
    __shared__ unsigned sb1, sustar;
    __shared__ int skrem;
    __shared__ float red[256];
    int slot = blockIdx.x;
    if (slot >= g_NR) return;
    int t = threadIdx.x;
    const uint4* src = (const uint4*)&g_KEY[(size_t)slot*B];
    uint4* dst = (uint4*)sv;
    for (int i = t; i < B*2/16; i += 256) dst[i] = src[i];
    __syncthreads();
    const unsigned* sw = (const unsigned*)sv;    // 4096 packed words
    const int K = 6553;                          // S = sum of values >= v[6553]
    // pass 1: high byte
    hist[t] = 0; __syncthreads();
    for (int i = t; i < B/2; i += 256) {
        unsigned v = sw[i];
        atomicAdd(&hist[(v >> 8) & 255], 1u);
        atomicAdd(&hist[v >> 24], 1u);
    }
    __syncthreads();
    #pragma unroll
    for (int o = 1; o < 256; o <<= 1) {
        unsigned pv = (t >= o) ? hist[t-o] : 0u; __syncthreads();
        hist[t] += pv; __syncthreads();
    }
    {
        unsigned cin = hist[t], cex = t ? hist[t-1] : 0u;
        if (cin > (unsigned)K && cex <= (unsigned)K) { sb1 = (unsigned)t; skrem = K - (int)cex; }
    }
    __syncthreads();
    unsigned b1 = sb1; int k2 = skrem;
    __syncthreads();
    // pass 2: low byte among b1
    hist[t] = 0; __syncthreads();
    for (int i = t; i < B/2; i += 256) {
        unsigned v = sw[i];
        if (((v >> 8) & 255) == b1) atomicAdd(&hist[v & 255], 1u);
        if ((v >> 24) == b1)        atomicAdd(&hist[(v >> 16) & 255], 1u);
    }
    __syncthreads();
    #pragma unroll
    for (int o = 1; o < 256; o <<= 1) {
        unsigned pv = (t >= o) ? hist[t-o] : 0u; __syncthreads();
        hist[t] += pv; __syncthreads();
    }
    {
        unsigned cin = hist[t], cex = t ? hist[t-1] : 0u;
        if (cin > (unsigned)k2 && cex <= (unsigned)k2) sustar = (b1 << 8) | (unsigned)t;
    }
    __syncthreads();
    unsigned ustar = sustar;
    float s = 0.f;
    for (int i = t; i < B/2; i += 256) {
        unsigned v = sw[i];
        unsigned klo = v & 0xFFFFu, khi = v >> 16;
        if (klo >= ustar) s += __expf(5.0f * dec_key(klo));
        if (khi >= ustar) s += __expf(5.0f * dec_key(khi));
    }
    red[t] = s; __syncthreads();
    for (int o = 128; o > 0; o >>= 1) { if (t < o) red[t] += red[t+o]; __syncthreads(); }
    if (t == 0) g_S[g_rows[slot]] = red[0];
}

// ---------------- fp32 radix select (k-th smallest) for pair threshold -------
__device__ unsigned radix_select32(const unsigned* sv, int n, int k,
                                   unsigned* hist, unsigned* spre, int* skrem) {
    int t = threadIdx.x;
    if (t == 0) { *spre = 0u; *skrem = k; }
    __syncthreads();
    for (int shift = 24; shift >= 0; shift -= 8) {
        hist[t] = 0u;
        __syncthreads();
        unsigned pre = *spre;
        unsigned hm  = (shift == 24) ? 0u : (0xFFFFFFFFu << (shift + 8));
        for (int c = t; c < n; c += 256) {
            unsigned u = sv[c];
            if ((u & hm) == pre) atomicAdd(&hist[(u >> shift) & 255], 1u);
        }
        __syncthreads();
        #pragma unroll
        for (int o = 1; o < 256; o <<= 1) {
            unsigned v = (t >= o) ? hist[t-o] : 0u; __syncthreads();
            hist[t] += v; __syncthreads();
        }
        unsigned kr  = (unsigned)*skrem;
        unsigned cin = hist[t];
        unsigned cex = t ? hist[t-1] : 0u;
        __syncthreads();
        if (cin > kr && cex <= kr) {
            *spre  = pre | ((unsigned)t << shift);
            *skrem = (int)(kr - cex);
        }
        __syncthreads();
    }
    return *spre;
}

__global__ void k_pairthr() {
    __shared__ unsigned pv[P];
    __shared__ unsigned hist[256];
    __shared__ unsigned spre; __shared__ int skrem;
    int t = threadIdx.x;
    for (int c = t; c < P; c += 256) pv[c] = __float_as_uint(g_pos[c]);
    __syncthreads();
    unsigned u = radix_select32(pv, P, 819, hist, &spre, &skrem);
    if (t == 0) g_thr = __uint_as_float(u);
}

// ---------------- active-pair moments ----------------------------------------
__global__ void k_stats() {
    __shared__ double r1[256], r2[256], r3[256], r4[256];
    __shared__ int rk[256];
    int t = threadIdx.x;
    float thr = g_thr;
    double p1 = 0, p2 = 0, p3 = 0, L = 0; int k = 0;
    for (int p = t; p < P; p += 256) {
        float v = g_pos[p];
        if (v <= thr) {
            double dv = (double)v;
            p1 += dv; p2 += dv*dv; p3 += dv*dv*dv; L += log(dv); k++;
        }
    }
    r1[t] = p1; r2[t] = p2; r3[t] = p3; r4[t] = L; rk[t] = k;
    __syncthreads();
    for (int o = 128; o > 0; o >>= 1) {
        if (t < o) { r1[t]+=r1[t+o]; r2[t]+=r2[t+o]; r3[t]+=r3[t+o]; r4[t]+=r4[t+o]; rk[t]+=rk[t+o]; }
        __syncthreads();
    }
    if (t == 0) {
        g_stats[0] = (double)rk[0]; g_stats[1] = r1[0]; g_stats[2] = r2[0];
        g_stats[3] = r3[0]; g_stats[4] = r4[0];
    }
}

// ---------------- closed-form loss -------------------------------------------
__global__ void k_final(const int* __restrict__ pp, float* __restrict__ out) {
    __shared__ double red[256];
    int t = threadIdx.x;
    double kact = g_stats[0], P1 = g_stats[1], P2 = g_stats[2], P3 = g_stats[3], L = g_stats[4];
    float thr = g_thr;
    double acc = 0.0;
    for (int s = t; s < 2*P; s += 256) {
        int pidx = s >> 1, side = s & 1;
        double S = (double)g_S[pp[pidx*2 + side]];
        if ((double)thr / S < 0.02) {
            double inv = 1.0 / S;
            acc += kact*log(S) - L + P1*inv - 0.5*P2*inv*inv + (1.0/3.0)*P3*inv*inv*inv;
        } else {
            for (int p = 0; p < P; ++p) {
                float pv = g_pos[p];
                if (pv <= thr) acc += log1p(S / (double)pv);
            }
        }
    }
    red[t] = acc; __syncthreads();
    for (int o = 128; o > 0; o >>= 1) { if (t < o) red[t] += red[t+o]; __syncthreads(); }
    if (t == 0) out[0] = (float)(red[0] / (2.0 * (double)P));
}

// ---------------- launch -----------------------------------------------------
extern "C" void kernel_launch(void* const* d_in, const int* in_sizes, int n_in,
                              void* d_out, int out_size) {
    const float* emb;
    const int*   pairs;
    if (in_sizes[0] == B*D) { emb = (const float*)d_in[0]; pairs = (const int*)d_in[1]; }
    else                    { emb = (const float*)d_in[1]; pairs = (const int*)d_in[0]; }
    float* out = (float*)d_out;

    cudaFuncSetAttribute(k_gemm_mma, cudaFuncAttributeMaxDynamicSharedMemorySize, GEMM_SMEM);

    k_clear    <<<(B*MASKW + 255)/256, 256>>>();
    k_normalize<<<B, 256>>>(emb);
    k_pairs    <<<P/8, 256>>>(pairs);
    k_compact  <<<B/256, 256>>>();
    k_gemm_mma <<<dim3(64, 64), 128, GEMM_SMEM>>>();
    k_select   <<<B, 256>>>();
    k_pairthr  <<<1, 256>>>();
    k_stats    <<<1, 256>>>();
    k_final    <<<1, 256>>>(pairs, out);
}